// round 7
// baseline (speedup 1.0000x reference)
#include <cuda_runtime.h>
#include <cuda_fp16.h>
#include <cstdint>

#define IN_F   4096
#define OUT_F  11008
#define M_TOT  8192

#define BM 64
#define BN 128
#define BK 32
#define NSTAGE 3
#define KT_CNT (IN_F / BK)   // 128
#define ASTR 40              // row stride in halves (64B data + 16B pad)

__device__ __align__(16) __half g_W[(size_t)OUT_F * IN_F];
__device__ __align__(16) __half g_X[(size_t)M_TOT * IN_F];

static __device__ __forceinline__ uint32_t smem_u32(const void* p) {
    return (uint32_t)__cvta_generic_to_shared(p);
}
static __device__ __forceinline__ void cp16(uint32_t dst, const void* src) {
    asm volatile("cp.async.cg.shared.global [%0], [%1], 16;\n" :: "r"(dst), "l"(src));
}

// ---------------------------------------------------------------------------
// Fused prep: blocks [0, XBLK) do xscale, blocks [XBLK, XBLK+QBLK) do dequant.
// ---------------------------------------------------------------------------
#define XBLK ((M_TOT * IN_F / 8) / 256)              // 16384
#define QBLK ((OUT_F * (IN_F / 2) / 4) / 256)        // 5504

__global__ __launch_bounds__(256)
void prep_kernel(const float* __restrict__ x, const float* __restrict__ iscale,
                 const int* __restrict__ qw, const float* __restrict__ scales,
                 const float* __restrict__ zeros) {
    if (blockIdx.x < XBLK) {
        int idx = blockIdx.x * 256 + threadIdx.x;
        const float4* xp = (const float4*)x;
        float4 a = xp[2 * idx], b = xp[2 * idx + 1];
        int k4 = (2 * idx) & 1023;
        float4 sa = ((const float4*)iscale)[k4];
        float4 sb = ((const float4*)iscale)[k4 + 1];
        uint4 r;
        __half2 h;
        h = __floats2half2_rn(a.x * sa.x, a.y * sa.y); r.x = *reinterpret_cast<uint32_t*>(&h);
        h = __floats2half2_rn(a.z * sa.z, a.w * sa.w); r.y = *reinterpret_cast<uint32_t*>(&h);
        h = __floats2half2_rn(b.x * sb.x, b.y * sb.y); r.z = *reinterpret_cast<uint32_t*>(&h);
        h = __floats2half2_rn(b.z * sb.z, b.w * sb.w); r.w = *reinterpret_cast<uint32_t*>(&h);
        ((uint4*)g_X)[idx] = r;
    } else {
        int idx = (blockIdx.x - XBLK) * 256 + threadIdx.x;
        int4 v = ((const int4*)qw)[idx];
        int o  = idx >> 9;
        int jq = idx & 511;
        int g  = jq >> 4;
        float s  = scales[o * 32 + g];
        float zs = -zeros[o * 32 + g] * s;
        uint4 outv;
        __half2 h;
        h = __floats2half2_rn((float)((v.x >> 4) & 15) * s + zs, (float)(v.x & 15) * s + zs);
        outv.x = *reinterpret_cast<uint32_t*>(&h);
        h = __floats2half2_rn((float)((v.y >> 4) & 15) * s + zs, (float)(v.y & 15) * s + zs);
        outv.y = *reinterpret_cast<uint32_t*>(&h);
        h = __floats2half2_rn((float)((v.z >> 4) & 15) * s + zs, (float)(v.z & 15) * s + zs);
        outv.z = *reinterpret_cast<uint32_t*>(&h);
        h = __floats2half2_rn((float)((v.w >> 4) & 15) * s + zs, (float)(v.w & 15) * s + zs);
        outv.w = *reinterpret_cast<uint32_t*>(&h);
        ((uint4*)g_W)[(size_t)o * 512 + jq] = outv;
    }
}

// ---------------------------------------------------------------------------
// GEMM: BM=64, BN=128, 4 warps (2x2), 32x64 warp tile, BK=32, 3-stage cp.async,
// 4 CTAs/SM (4 independent barrier domains per SM).
// ---------------------------------------------------------------------------
__global__ __launch_bounds__(128, 4)
void gemm_kernel(const float* __restrict__ bias, float* __restrict__ C) {
    extern __shared__ __half smem[];
    __half* smA = smem;                         // NSTAGE * BM * ASTR
    __half* smB = smem + NSTAGE * BM * ASTR;    // NSTAGE * BN * ASTR

    const int tid  = threadIdx.x;
    const int lane = tid & 31;
    const int wid  = tid >> 5;
    const int wm   = wid & 1;    // 2 warp rows of 32
    const int wn   = wid >> 1;   // 2 warp cols of 64
    const int m0   = blockIdx.y * BM;
    const int n0   = blockIdx.x * BN;

    const char* gA = (const char*)(g_X + (size_t)m0 * IN_F);
    const char* gB = (const char*)(g_W + (size_t)n0 * IN_F);

    float acc[2][8][4];
    #pragma unroll
    for (int i = 0; i < 2; i++)
        #pragma unroll
        for (int j = 0; j < 8; j++)
            #pragma unroll
            for (int k = 0; k < 4; k++) acc[i][j][k] = 0.f;

    const int rA = tid >> 2, cA = tid & 3;
    auto issue = [&](int kt, int slot) {
        __half* sA = smA + slot * (BM * ASTR);
        __half* sB = smB + slot * (BN * ASTR);
        size_t koff = (size_t)kt * (BK * 2);
        #pragma unroll
        for (int i = 0; i < 2; i++) {          // A: 256 chunks
            int r = rA + i * 32;
            cp16(smem_u32(sA + r * ASTR + cA * 8),
                 gA + (size_t)r * (IN_F * 2) + koff + cA * 16);
        }
        #pragma unroll
        for (int i = 0; i < 4; i++) {          // B: 512 chunks
            int r = rA + i * 32;
            cp16(smem_u32(sB + r * ASTR + cA * 8),
                 gB + (size_t)r * (IN_F * 2) + koff + cA * 16);
        }
        asm volatile("cp.async.commit_group;\n");
    };

    issue(0, 0);
    issue(1, 1);

    int cslot = 0, pslot = 2;
    for (int kt = 0; kt < KT_CNT; kt++) {
        asm volatile("cp.async.wait_group 1;\n");
        __syncthreads();
        if (kt + 2 < KT_CNT) issue(kt + 2, pslot);
        else asm volatile("cp.async.commit_group;\n");

        uint32_t a_base = smem_u32(smA + cslot * (BM * ASTR));
        uint32_t b_base = smem_u32(smB + cslot * (BN * ASTR));

        #pragma unroll
        for (int kk = 0; kk < 2; kk++) {
            uint32_t a[2][4];
            #pragma unroll
            for (int mt = 0; mt < 2; mt++) {
                int row = wm * 32 + mt * 16 + (lane & 15);
                int col = kk * 16 + (lane >> 4) * 8;
                uint32_t addr = a_base + (uint32_t)(row * ASTR + col) * 2;
                asm volatile("ldmatrix.sync.aligned.m8n8.x4.shared.b16 {%0,%1,%2,%3}, [%4];"
                    : "=r"(a[mt][0]), "=r"(a[mt][1]), "=r"(a[mt][2]), "=r"(a[mt][3])
                    : "r"(addr));
            }
            uint32_t b[8][2];
            #pragma unroll
            for (int ntp = 0; ntp < 4; ntp++) {
                int mi = lane >> 3, r = lane & 7;
                int n = wn * 64 + ntp * 16 + (mi >> 1) * 8 + r;
                int k = kk * 16 + (mi & 1) * 8;
                uint32_t addr = b_base + (uint32_t)(n * ASTR + k) * 2;
                uint32_t r0, r1, r2, r3;
                asm volatile("ldmatrix.sync.aligned.m8n8.x4.shared.b16 {%0,%1,%2,%3}, [%4];"
                    : "=r"(r0), "=r"(r1), "=r"(r2), "=r"(r3) : "r"(addr));
                b[2 * ntp][0]     = r0; b[2 * ntp][1]     = r1;
                b[2 * ntp + 1][0] = r2; b[2 * ntp + 1][1] = r3;
            }
            #pragma unroll
            for (int mt = 0; mt < 2; mt++)
                #pragma unroll
                for (int nt = 0; nt < 8; nt++) {
                    asm volatile(
                        "mma.sync.aligned.m16n8k16.row.col.f32.f16.f16.f32 "
                        "{%0,%1,%2,%3}, {%4,%5,%6,%7}, {%8,%9}, {%0,%1,%2,%3};"
                        : "+f"(acc[mt][nt][0]), "+f"(acc[mt][nt][1]),
                          "+f"(acc[mt][nt][2]), "+f"(acc[mt][nt][3])
                        : "r"(a[mt][0]), "r"(a[mt][1]), "r"(a[mt][2]), "r"(a[mt][3]),
                          "r"(b[nt][0]), "r"(b[nt][1]));
                }
        }

        cslot = (cslot + 1 == NSTAGE) ? 0 : cslot + 1;
        pslot = (pslot + 1 == NSTAGE) ? 0 : pslot + 1;
    }

    #pragma unroll
    for (int mt = 0; mt < 2; mt++) {
        int row = m0 + wm * 32 + mt * 16 + (lane >> 2);
        #pragma unroll
        for (int nt = 0; nt < 8; nt++) {
            int col = n0 + wn * 64 + nt * 8 + (lane & 3) * 2;
            float2 bv = *reinterpret_cast<const float2*>(bias + col);
            float2 v0 = make_float2(acc[mt][nt][0] + bv.x, acc[mt][nt][1] + bv.y);
            float2 v1 = make_float2(acc[mt][nt][2] + bv.x, acc[mt][nt][3] + bv.y);
            *reinterpret_cast<float2*>(C + (size_t)row * OUT_F + col)       = v0;
            *reinterpret_cast<float2*>(C + (size_t)(row + 8) * OUT_F + col) = v1;
        }
    }
}

// ---------------------------------------------------------------------------
extern "C" void kernel_launch(void* const* d_in, const int* in_sizes, int n_in,
                              void* d_out, int out_size) {
    const float* x      = (const float*)d_in[0];
    const int*   qw     = (const int*)  d_in[1];
    const float* scales = (const float*)d_in[2];
    const float* zeros  = (const float*)d_in[3];
    const float* iscale = (const float*)d_in[4];
    const float* bias   = (const float*)d_in[5];
    float* out = (float*)d_out;

    prep_kernel<<<XBLK + QBLK, 256>>>(x, iscale, qw, scales, zeros);

    constexpr int SMEM_BYTES = NSTAGE * (BM + BN) * ASTR * 2;   // 46080
    cudaFuncSetAttribute(gemm_kernel, cudaFuncAttributeMaxDynamicSharedMemorySize, SMEM_BYTES);
    dim3 grid(OUT_F / BN, M_TOT / BM);   // 86 x 128
    gemm_kernel<<<grid, 128, SMEM_BYTES>>>(bias, out);
}

// round 8
// speedup vs baseline: 1.1569x; 1.1569x over previous
#include <cuda_runtime.h>
#include <cuda_fp16.h>
#include <cstdint>

#define IN_F   4096
#define OUT_F  11008
#define M_TOT  8192

#define BM 128
#define BN 128
#define BK 32
#define NSTAGE 4
#define KT_CNT (IN_F / BK)   // 128
#define ASTR 40              // row stride in halves (64B data + 16B pad)

__device__ __align__(16) __half g_W[(size_t)OUT_F * IN_F];
__device__ __align__(16) __half g_X[(size_t)M_TOT * IN_F];

static __device__ __forceinline__ uint32_t smem_u32(const void* p) {
    return (uint32_t)__cvta_generic_to_shared(p);
}
static __device__ __forceinline__ void cp16(uint32_t dst, const void* src) {
    asm volatile("cp.async.cg.shared.global [%0], [%1], 16;\n" :: "r"(dst), "l"(src));
}
static __device__ __forceinline__ void ldsm4(uint32_t* d, uint32_t addr) {
    asm volatile("ldmatrix.sync.aligned.m8n8.x4.shared.b16 {%0,%1,%2,%3}, [%4];"
        : "=r"(d[0]), "=r"(d[1]), "=r"(d[2]), "=r"(d[3]) : "r"(addr));
}

// ---------------------------------------------------------------------------
// Fused prep: blocks [0, XBLK) do xscale, blocks [XBLK, XBLK+QBLK) do dequant.
// ---------------------------------------------------------------------------
#define XBLK ((M_TOT * IN_F / 8) / 256)              // 16384
#define QBLK ((OUT_F * (IN_F / 2) / 4) / 256)        // 5504

__global__ __launch_bounds__(256)
void prep_kernel(const float* __restrict__ x, const float* __restrict__ iscale,
                 const int* __restrict__ qw, const float* __restrict__ scales,
                 const float* __restrict__ zeros) {
    if (blockIdx.x < XBLK) {
        int idx = blockIdx.x * 256 + threadIdx.x;
        const float4* xp = (const float4*)x;
        float4 a = xp[2 * idx], b = xp[2 * idx + 1];
        int k4 = (2 * idx) & 1023;
        float4 sa = ((const float4*)iscale)[k4];
        float4 sb = ((const float4*)iscale)[k4 + 1];
        uint4 r;
        __half2 h;
        h = __floats2half2_rn(a.x * sa.x, a.y * sa.y); r.x = *reinterpret_cast<uint32_t*>(&h);
        h = __floats2half2_rn(a.z * sa.z, a.w * sa.w); r.y = *reinterpret_cast<uint32_t*>(&h);
        h = __floats2half2_rn(b.x * sb.x, b.y * sb.y); r.z = *reinterpret_cast<uint32_t*>(&h);
        h = __floats2half2_rn(b.z * sb.z, b.w * sb.w); r.w = *reinterpret_cast<uint32_t*>(&h);
        ((uint4*)g_X)[idx] = r;
    } else {
        int idx = (blockIdx.x - XBLK) * 256 + threadIdx.x;
        int4 v = ((const int4*)qw)[idx];
        int o  = idx >> 9;
        int jq = idx & 511;
        int g  = jq >> 4;
        float s  = scales[o * 32 + g];
        float zs = -zeros[o * 32 + g] * s;
        uint4 outv;
        __half2 h;
        h = __floats2half2_rn((float)((v.x >> 4) & 15) * s + zs, (float)(v.x & 15) * s + zs);
        outv.x = *reinterpret_cast<uint32_t*>(&h);
        h = __floats2half2_rn((float)((v.y >> 4) & 15) * s + zs, (float)(v.y & 15) * s + zs);
        outv.y = *reinterpret_cast<uint32_t*>(&h);
        h = __floats2half2_rn((float)((v.z >> 4) & 15) * s + zs, (float)(v.z & 15) * s + zs);
        outv.z = *reinterpret_cast<uint32_t*>(&h);
        h = __floats2half2_rn((float)((v.w >> 4) & 15) * s + zs, (float)(v.w & 15) * s + zs);
        outv.w = *reinterpret_cast<uint32_t*>(&h);
        ((uint4*)g_W)[(size_t)o * 512 + jq] = outv;
    }
}

// ---------------------------------------------------------------------------
// GEMM: BM=BN=128, 8 warps (4x2), 32x64 warp tile, BK=32, 4-stage cp.async,
// 2 CTAs/SM, register-level software pipelining of LDSM across kk AND kt.
// ---------------------------------------------------------------------------
__global__ __launch_bounds__(256, 2)
void gemm_kernel(const float* __restrict__ bias, float* __restrict__ C) {
    extern __shared__ __half smem[];
    __half* smA = smem;                         // NSTAGE * BM * ASTR
    __half* smB = smem + NSTAGE * BM * ASTR;    // NSTAGE * BN * ASTR

    const int tid  = threadIdx.x;
    const int lane = tid & 31;
    const int wid  = tid >> 5;
    const int wm   = wid & 3;    // 4 warp rows of 32
    const int wn   = wid >> 2;   // 2 warp cols of 64
    const int m0   = blockIdx.y * BM;
    const int n0   = blockIdx.x * BN;

    const char* gA = (const char*)(g_X + (size_t)m0 * IN_F);
    const char* gB = (const char*)(g_W + (size_t)n0 * IN_F);

    float acc[2][8][4];
    #pragma unroll
    for (int i = 0; i < 2; i++)
        #pragma unroll
        for (int j = 0; j < 8; j++)
            #pragma unroll
            for (int k = 0; k < 4; k++) acc[i][j][k] = 0.f;

    // lane-constant smem read offsets (bytes within a stage), kk=0; kk=1 adds 32B
    uint32_t aoffs[2], boffs[4];
    #pragma unroll
    for (int mt = 0; mt < 2; mt++) {
        int row = wm * 32 + mt * 16 + (lane & 15);
        int col = (lane >> 4) * 8;
        aoffs[mt] = (uint32_t)(row * ASTR + col) * 2;
    }
    {
        int mi = lane >> 3, r = lane & 7;
        #pragma unroll
        for (int ntp = 0; ntp < 4; ntp++) {
            int n = wn * 64 + ntp * 16 + (mi >> 1) * 8 + r;
            int k = (mi & 1) * 8;
            boffs[ntp] = (uint32_t)(n * ASTR + k) * 2;
        }
    }

    const int rA = tid >> 2, cA = tid & 3;
    auto issue = [&](int kt) {
        int slot = kt & (NSTAGE - 1);
        __half* sA = smA + slot * (BM * ASTR);
        __half* sB = smB + slot * (BN * ASTR);
        size_t koff = (size_t)kt * (BK * 2);
        #pragma unroll
        for (int i = 0; i < 2; i++) {
            int r = rA + i * 64;
            cp16(smem_u32(sA + r * ASTR + cA * 8),
                 gA + (size_t)r * (IN_F * 2) + koff + cA * 16);
            cp16(smem_u32(sB + r * ASTR + cA * 8),
                 gB + (size_t)r * (IN_F * 2) + koff + cA * 16);
        }
        asm volatile("cp.async.commit_group;\n");
    };

    uint32_t abuf[2][2][4];   // [kk][mt][frag]
    uint32_t bbuf[2][8][2];   // [kk][nt][frag]

    auto loadA = [&](uint32_t (*ab)[4], uint32_t base, uint32_t kkoff) {
        #pragma unroll
        for (int mt = 0; mt < 2; mt++) ldsm4(ab[mt], base + aoffs[mt] + kkoff);
    };
    auto loadB = [&](uint32_t (*bb)[2], uint32_t base, uint32_t kkoff) {
        #pragma unroll
        for (int ntp = 0; ntp < 4; ntp++) {
            uint32_t t[4];
            ldsm4(t, base + boffs[ntp] + kkoff);
            bb[2 * ntp][0] = t[0]; bb[2 * ntp][1] = t[1];
            bb[2 * ntp + 1][0] = t[2]; bb[2 * ntp + 1][1] = t[3];
        }
    };
    auto domma = [&](uint32_t (*ab)[4], uint32_t (*bb)[2]) {
        #pragma unroll
        for (int mt = 0; mt < 2; mt++)
            #pragma unroll
            for (int nt = 0; nt < 8; nt++) {
                asm volatile(
                    "mma.sync.aligned.m16n8k16.row.col.f32.f16.f16.f32 "
                    "{%0,%1,%2,%3}, {%4,%5,%6,%7}, {%8,%9}, {%0,%1,%2,%3};"
                    : "+f"(acc[mt][nt][0]), "+f"(acc[mt][nt][1]),
                      "+f"(acc[mt][nt][2]), "+f"(acc[mt][nt][3])
                    : "r"(ab[mt][0]), "r"(ab[mt][1]), "r"(ab[mt][2]), "r"(ab[mt][3]),
                      "r"(bb[nt][0]), "r"(bb[nt][1]));
            }
    };

    issue(0); issue(1); issue(2);
    asm volatile("cp.async.wait_group 1;\n");   // slots 0,1 complete (this thread)
    __syncthreads();                            // CTA-wide

    {   // prime buf0 with (slot 0, kk0)
        uint32_t a0 = smem_u32(smA);
        uint32_t b0 = smem_u32(smB);
        loadA(abuf[0], a0, 0);
        loadB(bbuf[0], b0, 0);
    }

    for (int kt = 0; kt < KT_CNT; kt++) {
        asm volatile("cp.async.wait_group 1;\n");  // commits <= kt+1 done
        __syncthreads();

        int cs = kt & (NSTAGE - 1);
        uint32_t ca = smem_u32(smA + cs * (BM * ASTR));
        uint32_t cb = smem_u32(smB + cs * (BN * ASTR));

        // load kk1 of current tile
        loadA(abuf[1], ca, 32);
        loadB(bbuf[1], cb, 32);

        if (kt + 3 < KT_CNT) issue(kt + 3);
        else asm volatile("cp.async.commit_group;\n");

        // MMA kk0 (regs loaded last iteration / prologue)
        domma(abuf[0], bbuf[0]);

        // prefetch kk0 of NEXT tile (slot kt+1 is complete: wait covered it)
        if (kt + 1 < KT_CNT) {
            int ns = (kt + 1) & (NSTAGE - 1);
            uint32_t na = smem_u32(smA + ns * (BM * ASTR));
            uint32_t nb = smem_u32(smB + ns * (BN * ASTR));
            loadA(abuf[0], na, 0);
            loadB(bbuf[0], nb, 0);
        }

        // MMA kk1
        domma(abuf[1], bbuf[1]);
    }

    #pragma unroll
    for (int mt = 0; mt < 2; mt++) {
        int row = m0 + wm * 32 + mt * 16 + (lane >> 2);
        #pragma unroll
        for (int nt = 0; nt < 8; nt++) {
            int col = n0 + wn * 64 + nt * 8 + (lane & 3) * 2;
            float2 bv = *reinterpret_cast<const float2*>(bias + col);
            float2 v0 = make_float2(acc[mt][nt][0] + bv.x, acc[mt][nt][1] + bv.y);
            float2 v1 = make_float2(acc[mt][nt][2] + bv.x, acc[mt][nt][3] + bv.y);
            *reinterpret_cast<float2*>(C + (size_t)row * OUT_F + col)       = v0;
            *reinterpret_cast<float2*>(C + (size_t)(row + 8) * OUT_F + col) = v1;
        }
    }
}

// ---------------------------------------------------------------------------
extern "C" void kernel_launch(void* const* d_in, const int* in_sizes, int n_in,
                              void* d_out, int out_size) {
    const float* x      = (const float*)d_in[0];
    const int*   qw     = (const int*)  d_in[1];
    const float* scales = (const float*)d_in[2];
    const float* zeros  = (const float*)d_in[3];
    const float* iscale = (const float*)d_in[4];
    const float* bias   = (const float*)d_in[5];
    float* out = (float*)d_out;

    prep_kernel<<<XBLK + QBLK, 256>>>(x, iscale, qw, scales, zeros);

    constexpr int SMEM_BYTES = NSTAGE * (BM + BN) * ASTR * 2;   // 81920
    cudaFuncSetAttribute(gemm_kernel, cudaFuncAttributeMaxDynamicSharedMemorySize, SMEM_BYTES);
    dim3 grid(OUT_F / BN, M_TOT / BM);   // 86 x 64
    gemm_kernel<<<grid, 256, SMEM_BYTES>>>(bias, out);
}

// round 9
// speedup vs baseline: 1.2561x; 1.0858x over previous
#include <cuda_runtime.h>
#include <cuda_fp16.h>
#include <cstdint>

#define IN_F   4096
#define OUT_F  11008
#define M_TOT  8192

#define BM 128
#define BN 128
#define BK 32
#define NSTAGE 4
#define KT_CNT (IN_F / BK)   // 128
#define ASTR 40              // row stride in halves (64B data + 16B pad)

__device__ __align__(16) __half g_W[(size_t)OUT_F * IN_F];
__device__ __align__(16) __half g_X[(size_t)M_TOT * IN_F];

static __device__ __forceinline__ uint32_t smem_u32(const void* p) {
    return (uint32_t)__cvta_generic_to_shared(p);
}
static __device__ __forceinline__ void cp16(uint32_t dst, const void* src) {
    asm volatile("cp.async.cg.shared.global [%0], [%1], 16;\n" :: "r"(dst), "l"(src));
}
static __device__ __forceinline__ void ldsm4(uint32_t* d, uint32_t addr) {
    asm volatile("ldmatrix.sync.aligned.m8n8.x4.shared.b16 {%0,%1,%2,%3}, [%4];"
        : "=r"(d[0]), "=r"(d[1]), "=r"(d[2]), "=r"(d[3]) : "r"(addr));
}

// ---------------------------------------------------------------------------
// Fused prep: blocks [0, XBLK) do xscale, blocks [XBLK, XBLK+QBLK) do dequant.
// ---------------------------------------------------------------------------
#define XBLK ((M_TOT * IN_F / 8) / 256)              // 16384
#define QBLK ((OUT_F * (IN_F / 2) / 4) / 256)        // 5504

__global__ __launch_bounds__(256)
void prep_kernel(const float* __restrict__ x, const float* __restrict__ iscale,
                 const int* __restrict__ qw, const float* __restrict__ scales,
                 const float* __restrict__ zeros) {
    if (blockIdx.x < XBLK) {
        int idx = blockIdx.x * 256 + threadIdx.x;
        const float4* xp = (const float4*)x;
        float4 a = xp[2 * idx], b = xp[2 * idx + 1];
        int k4 = (2 * idx) & 1023;
        float4 sa = ((const float4*)iscale)[k4];
        float4 sb = ((const float4*)iscale)[k4 + 1];
        uint4 r;
        __half2 h;
        h = __floats2half2_rn(a.x * sa.x, a.y * sa.y); r.x = *reinterpret_cast<uint32_t*>(&h);
        h = __floats2half2_rn(a.z * sa.z, a.w * sa.w); r.y = *reinterpret_cast<uint32_t*>(&h);
        h = __floats2half2_rn(b.x * sb.x, b.y * sb.y); r.z = *reinterpret_cast<uint32_t*>(&h);
        h = __floats2half2_rn(b.z * sb.z, b.w * sb.w); r.w = *reinterpret_cast<uint32_t*>(&h);
        ((uint4*)g_X)[idx] = r;
    } else {
        int idx = (blockIdx.x - XBLK) * 256 + threadIdx.x;
        int4 v = ((const int4*)qw)[idx];
        int o  = idx >> 9;
        int jq = idx & 511;
        int g  = jq >> 4;
        float s  = scales[o * 32 + g];
        float zs = -zeros[o * 32 + g] * s;
        uint4 outv;
        __half2 h;
        h = __floats2half2_rn((float)((v.x >> 4) & 15) * s + zs, (float)(v.x & 15) * s + zs);
        outv.x = *reinterpret_cast<uint32_t*>(&h);
        h = __floats2half2_rn((float)((v.y >> 4) & 15) * s + zs, (float)(v.y & 15) * s + zs);
        outv.y = *reinterpret_cast<uint32_t*>(&h);
        h = __floats2half2_rn((float)((v.z >> 4) & 15) * s + zs, (float)(v.z & 15) * s + zs);
        outv.z = *reinterpret_cast<uint32_t*>(&h);
        h = __floats2half2_rn((float)((v.w >> 4) & 15) * s + zs, (float)(v.w & 15) * s + zs);
        outv.w = *reinterpret_cast<uint32_t*>(&h);
        ((uint4*)g_W)[(size_t)o * 512 + jq] = outv;
    }
}

// ---------------------------------------------------------------------------
// GEMM: BM=BN=128, 4 warps (2x2), 64x64 warp tile, BK=32, 4-stage cp.async,
// 2 CTAs/SM, register-level software pipelining of LDSM across kk AND kt.
// 64x64 warp tile halves smem read traffic per MAC vs 32x64 (L1 was co-limit).
// ---------------------------------------------------------------------------
__global__ __launch_bounds__(128, 2)
void gemm_kernel(const float* __restrict__ bias, float* __restrict__ C) {
    extern __shared__ __half smem[];
    __half* smA = smem;                         // NSTAGE * BM * ASTR
    __half* smB = smem + NSTAGE * BM * ASTR;    // NSTAGE * BN * ASTR

    const int tid  = threadIdx.x;
    const int lane = tid & 31;
    const int wid  = tid >> 5;
    const int wm   = wid & 1;    // 2 warp rows of 64
    const int wn   = wid >> 1;   // 2 warp cols of 64
    const int m0   = blockIdx.y * BM;
    const int n0   = blockIdx.x * BN;

    const char* gA = (const char*)(g_X + (size_t)m0 * IN_F);
    const char* gB = (const char*)(g_W + (size_t)n0 * IN_F);

    float acc[4][8][4];
    #pragma unroll
    for (int i = 0; i < 4; i++)
        #pragma unroll
        for (int j = 0; j < 8; j++)
            #pragma unroll
            for (int k = 0; k < 4; k++) acc[i][j][k] = 0.f;

    // lane-constant smem read offsets (bytes within a stage); kk=1 adds 32B
    uint32_t aoffs[4], boffs[4];
    #pragma unroll
    for (int mt = 0; mt < 4; mt++) {
        int row = wm * 64 + mt * 16 + (lane & 15);
        int col = (lane >> 4) * 8;
        aoffs[mt] = (uint32_t)(row * ASTR + col) * 2;
    }
    {
        int mi = lane >> 3, r = lane & 7;
        #pragma unroll
        for (int ntp = 0; ntp < 4; ntp++) {
            int n = wn * 64 + ntp * 16 + (mi >> 1) * 8 + r;
            int k = (mi & 1) * 8;
            boffs[ntp] = (uint32_t)(n * ASTR + k) * 2;
        }
    }

    // loader mapping: 1024 chunks (A 512 + B 512) over 128 threads, 4+4 each
    const int rA = tid >> 2, cA = tid & 3;
    auto issue = [&](int kt) {
        int slot = kt & (NSTAGE - 1);
        __half* sA = smA + slot * (BM * ASTR);
        __half* sB = smB + slot * (BN * ASTR);
        size_t koff = (size_t)kt * (BK * 2);
        #pragma unroll
        for (int i = 0; i < 4; i++) {
            int r = rA + i * 32;
            cp16(smem_u32(sA + r * ASTR + cA * 8),
                 gA + (size_t)r * (IN_F * 2) + koff + cA * 16);
            cp16(smem_u32(sB + r * ASTR + cA * 8),
                 gB + (size_t)r * (IN_F * 2) + koff + cA * 16);
        }
        asm volatile("cp.async.commit_group;\n");
    };

    uint32_t abuf[2][4][4];   // [kk][mt][frag]
    uint32_t bbuf[2][8][2];   // [kk][nt][frag]

    auto loadA = [&](uint32_t (*ab)[4], uint32_t base, uint32_t kkoff) {
        #pragma unroll
        for (int mt = 0; mt < 4; mt++) ldsm4(ab[mt], base + aoffs[mt] + kkoff);
    };
    auto loadB = [&](uint32_t (*bb)[2], uint32_t base, uint32_t kkoff) {
        #pragma unroll
        for (int ntp = 0; ntp < 4; ntp++) {
            uint32_t t[4];
            ldsm4(t, base + boffs[ntp] + kkoff);
            bb[2 * ntp][0] = t[0]; bb[2 * ntp][1] = t[1];
            bb[2 * ntp + 1][0] = t[2]; bb[2 * ntp + 1][1] = t[3];
        }
    };
    auto domma = [&](uint32_t (*ab)[4], uint32_t (*bb)[2]) {
        #pragma unroll
        for (int mt = 0; mt < 4; mt++)
            #pragma unroll
            for (int nt = 0; nt < 8; nt++) {
                asm volatile(
                    "mma.sync.aligned.m16n8k16.row.col.f32.f16.f16.f32 "
                    "{%0,%1,%2,%3}, {%4,%5,%6,%7}, {%8,%9}, {%0,%1,%2,%3};"
                    : "+f"(acc[mt][nt][0]), "+f"(acc[mt][nt][1]),
                      "+f"(acc[mt][nt][2]), "+f"(acc[mt][nt][3])
                    : "r"(ab[mt][0]), "r"(ab[mt][1]), "r"(ab[mt][2]), "r"(ab[mt][3]),
                      "r"(bb[nt][0]), "r"(bb[nt][1]));
            }
    };

    issue(0); issue(1); issue(2);
    asm volatile("cp.async.wait_group 1;\n");   // slots 0,1 complete (this thread)
    __syncthreads();                            // CTA-wide

    {   // prime buf0 with (slot 0, kk0)
        loadA(abuf[0], smem_u32(smA), 0);
        loadB(bbuf[0], smem_u32(smB), 0);
    }

    for (int kt = 0; kt < KT_CNT; kt++) {
        asm volatile("cp.async.wait_group 1;\n");  // slots kt, kt+1 ready
        __syncthreads();

        int cs = kt & (NSTAGE - 1);
        uint32_t ca = smem_u32(smA + cs * (BM * ASTR));
        uint32_t cb = smem_u32(smB + cs * (BN * ASTR));

        // load kk1 of current tile
        loadA(abuf[1], ca, 32);
        loadB(bbuf[1], cb, 32);

        if (kt + 3 < KT_CNT) issue(kt + 3);
        else asm volatile("cp.async.commit_group;\n");

        // MMA kk0 (regs loaded last iteration / prologue)
        domma(abuf[0], bbuf[0]);

        // prefetch kk0 of NEXT tile (slot kt+1 complete: wait covered it)
        if (kt + 1 < KT_CNT) {
            int ns = (kt + 1) & (NSTAGE - 1);
            loadA(abuf[0], smem_u32(smA + ns * (BM * ASTR)), 0);
            loadB(bbuf[0], smem_u32(smB + ns * (BN * ASTR)), 0);
        }

        // MMA kk1
        domma(abuf[1], bbuf[1]);
    }

    #pragma unroll
    for (int mt = 0; mt < 4; mt++) {
        int row = m0 + wm * 64 + mt * 16 + (lane >> 2);
        #pragma unroll
        for (int nt = 0; nt < 8; nt++) {
            int col = n0 + wn * 64 + nt * 8 + (lane & 3) * 2;
            float2 bv = *reinterpret_cast<const float2*>(bias + col);
            float2 v0 = make_float2(acc[mt][nt][0] + bv.x, acc[mt][nt][1] + bv.y);
            float2 v1 = make_float2(acc[mt][nt][2] + bv.x, acc[mt][nt][3] + bv.y);
            *reinterpret_cast<float2*>(C + (size_t)row * OUT_F + col)       = v0;
            *reinterpret_cast<float2*>(C + (size_t)(row + 8) * OUT_F + col) = v1;
        }
    }
}

// ---------------------------------------------------------------------------
extern "C" void kernel_launch(void* const* d_in, const int* in_sizes, int n_in,
                              void* d_out, int out_size) {
    const float* x      = (const float*)d_in[0];
    const int*   qw     = (const int*)  d_in[1];
    const float* scales = (const float*)d_in[2];
    const float* zeros  = (const float*)d_in[3];
    const float* iscale = (const float*)d_in[4];
    const float* bias   = (const float*)d_in[5];
    float* out = (float*)d_out;

    prep_kernel<<<XBLK + QBLK, 256>>>(x, iscale, qw, scales, zeros);

    constexpr int SMEM_BYTES = NSTAGE * (BM + BN) * ASTR * 2;   // 81920
    cudaFuncSetAttribute(gemm_kernel, cudaFuncAttributeMaxDynamicSharedMemorySize, SMEM_BYTES);
    dim3 grid(OUT_F / BN, M_TOT / BM);   // 86 x 64
    gemm_kernel<<<grid, 128, SMEM_BYTES>>>(bias, out);
}